// round 7
// baseline (speedup 1.0000x reference)
#include <cuda_runtime.h>
#include <cstdint>

#define KTOT   4194304
#define CHUNK  32                       // outputs per chain
#define WARM   128                      // warmup (redundant) steps per chain
#define TS     16                       // steps per tile
#define NT     ((WARM + CHUNK) / TS)    // 10 tiles
#define WTILES (WARM / TS)              // 8 warmup tiles
#define NCH    (KTOT / CHUNK)           // 131072 chains
#define CPW    64                       // chains per warp (f32x2 pair per thread)
#define NWARP  (NCH / CPW)              // 2048 warps
#define WPB    2                        // warps per block
#define TPB    (WPB * 32)
#define NBLK   (NWARP / WPB)            // 1024 blocks
#define PITCH  18                       // smem row pitch in floats (8B-aligned)

typedef unsigned long long u64;

__device__ __forceinline__ float frcp_ap(float x) {
    float r; asm("rcp.approx.ftz.f32 %0, %1;" : "=f"(r) : "f"(x)); return r;
}
__device__ __forceinline__ float fsqrt_ap(float x) {
    float r; asm("sqrt.approx.f32 %0, %1;" : "=f"(r) : "f"(x)); return r;
}
__device__ __forceinline__ u64 pack2(float a, float b) {
    u64 d; asm("mov.b64 %0, {%1, %2};" : "=l"(d)
               : "r"(__float_as_uint(a)), "r"(__float_as_uint(b)));
    return d;
}
__device__ __forceinline__ void unpack2(u64 v, float& a, float& b) {
    uint32_t x, y;
    asm("mov.b64 {%0, %1}, %2;" : "=r"(x), "=r"(y) : "l"(v));
    a = __uint_as_float(x); b = __uint_as_float(y);
}
__device__ __forceinline__ u64 fma2(u64 a, u64 b, u64 c) {
    u64 d; asm("fma.rn.f32x2 %0, %1, %2, %3;" : "=l"(d) : "l"(a), "l"(b), "l"(c));
    return d;
}
__device__ __forceinline__ u64 mul2(u64 a, u64 b) {
    u64 d; asm("mul.rn.f32x2 %0, %1, %2;" : "=l"(d) : "l"(a), "l"(b));
    return d;
}
__device__ __forceinline__ void cp_async8(uint32_t dst, const float* src) {
    asm volatile("cp.async.ca.shared.global [%0], [%1], 8;" :: "r"(dst), "l"(src));
}
#define CP_COMMIT() asm volatile("cp.async.commit_group;" ::: "memory")
#define CP_WAIT1()  asm volatile("cp.async.wait_group 1;"  ::: "memory")
#define CP_WAIT0()  asm volatile("cp.async.wait_group 0;"  ::: "memory")

struct C {
    u64 neg1, nu2, amu2, as2, bmu2, bs2, wmu2, ws2;   // packed (x==y) constants
    float nu, Amu, As, bmu, Bs, wmu, ws;              // scalar copies (guard path)
};

// One step for BOTH chains, packed. Bit-identical to the scalar sequence.
__device__ __forceinline__ void gas2(const u64 y2, u64& mu2, u64& s22, const C& c) {
    const u64 r  = fma2(mu2, c.neg1, y2);       // y - mu (exact, one rounding)
    const u64 rr = mul2(r, r);
    const u64 d  = fma2(c.nu2, s22, rr);
    float dA, dB; unpack2(d, dA, dB);
    const u64 q   = pack2(frcp_ap(dA), frcp_ap(dB));
    const u64 s2r = mul2(s22, r);
    const u64 mb  = fma2(c.bmu2, mu2, c.wmu2);  // off critical path
    const u64 sb  = fma2(c.bs2,  s22, c.ws2);   // off critical path
    const u64 N   = mul2(s2r, q);
    mu2 = fma2(c.amu2, N, mb);
    s22 = fma2(c.as2, mul2(N, r), sb);
}

// Scalar step (guard path only: warp 0, chains 0..3).
__device__ __forceinline__ void gas1(const float y, float& mu, float& s2, const C& c) {
    const float r_  = y - mu;
    const float rr  = r_ * r_;
    const float d   = fmaf(c.nu, s2, rr);
    const float q   = frcp_ap(d);
    const float s2r = s2 * r_;
    const float mb  = fmaf(c.bmu, mu, c.wmu);
    const float sb  = fmaf(c.Bs,  s2, c.ws);
    const float N   = s2r * q;
    mu = fmaf(c.Amu, N, mb);
    s2 = fmaf(c.As, N * r_, sb);
}

// Stage tile tau (64 chains x 16 steps, 4KB) with 8B cp.async, chain-major rows.
template<bool GUARD>
__device__ __forceinline__ void stage_tile(
    const int tau, const int wcb, const int lane,
    const float* __restrict__ y, float (*buf)[PITCH])
{
    const int r0  = lane >> 3;
    const int col = (lane & 7) * 2;
    uint32_t dst = (uint32_t)__cvta_generic_to_shared(&buf[r0][col]);
    const int gbase = (wcb + r0) * CHUNK - WARM + tau * TS + col;
    #pragma unroll
    for (int k = 0; k < 16; ++k) {
        int g = gbase + k * (4 * CHUNK);           // 4 rows per k
        if (GUARD) g = max(g, 0);                  // pre-t0 slots: skipped anyway
        cp_async8(dst + k * (4 * PITCH * 4), y + g);
    }
    CP_COMMIT();
}

// Packed compute of TS steps for the chain pair (A = row lane, B = row lane+32).
template<bool EMIT>
__device__ __forceinline__ void compute_tile2(
    const int lane, float (*bufc)[PITCH], float (*sg)[PITCH],
    u64& mu2, u64& s22, const C& c)
{
    #pragma unroll
    for (int s = 0; s < TS; s += 2) {
        const float2 ya = *reinterpret_cast<const float2*>(&bufc[lane][s]);
        const float2 yb = *reinterpret_cast<const float2*>(&bufc[lane + 32][s]);
        gas2(pack2(ya.x, yb.x), mu2, s22, c);
        if (EMIT) {
            float mA0, mB0, vA0, vB0;
            unpack2(mu2, mA0, mB0); unpack2(s22, vA0, vB0);
            gas2(pack2(ya.y, yb.y), mu2, s22, c);
            float mA1, mB1, vA1, vB1;
            unpack2(mu2, mA1, mB1); unpack2(s22, vA1, vB1);
            *reinterpret_cast<float2*>(&bufc[lane][s])      = make_float2(mA0, mA1);
            *reinterpret_cast<float2*>(&bufc[lane + 32][s]) = make_float2(mB0, mB1);
            *reinterpret_cast<float2*>(&sg[lane][s])        = make_float2(vA0, vA1);
            *reinterpret_cast<float2*>(&sg[lane + 32][s])   = make_float2(vB0, vB1);
        } else {
            gas2(pack2(ya.y, yb.y), mu2, s22, c);
        }
    }
}

// Guard compute (scalar, skip checks on chain A). Warmup tiles of warp 0 only.
__device__ __forceinline__ void compute_tile_guard(
    const int tau, const int lane, const int skipA,
    float (*bufc)[PITCH], u64& mu2, u64& s22, const C& c)
{
    float muA, muB, sA, sB;
    unpack2(mu2, muA, muB); unpack2(s22, sA, sB);
    #pragma unroll
    for (int s = 0; s < TS; ++s) {
        const float yA = bufc[lane][s];
        const float yB = bufc[lane + 32][s];
        if (tau * TS + s >= skipA) gas1(yA, muA, sA, c);
        gas1(yB, muB, sB, c);
    }
    mu2 = pack2(muA, muB); s22 = pack2(sA, sB);
}

// Coalesced flush: mu from bufc (in-place), sigma = sqrt(s2) from sg.
__device__ __forceinline__ void flush_tile(
    const int tau, const int wcb, const int lane,
    const float (*bufc)[PITCH], const float (*sg)[PITCH], float* __restrict__ out)
{
    const int r0  = lane >> 3;
    const int col = (lane & 7) * 2;
    const int ob  = (tau - WTILES) * TS;
    #pragma unroll
    for (int k = 0; k < 16; ++k) {
        const int row = r0 + 4 * k;
        const float2 m = *reinterpret_cast<const float2*>(&bufc[row][col]);
        float2 g = *reinterpret_cast<const float2*>(&sg[row][col]);
        g.x = fsqrt_ap(g.x); g.y = fsqrt_ap(g.y);   // sqrt off the hot loop
        const int gi = (wcb + row) * CHUNK + ob + col;
        *reinterpret_cast<float2*>(&out[gi])        = m;
        *reinterpret_cast<float2*>(&out[KTOT + gi]) = g;
    }
}

template<bool GUARD>
__device__ __forceinline__ void run_warp(
    const int wcb, const int lane,
    const float* __restrict__ y, float* __restrict__ out,
    float (*buf)[CPW][PITCH], float (*sg)[PITCH],
    u64 mu2, u64 s22, const C& c, const int skipA)
{
    stage_tile<GUARD>(0, wcb, lane, y, buf[0]);
    stage_tile<GUARD>(1, wcb, lane, y, buf[1]);
    #pragma unroll 1
    for (int t = 0; t < NT; ++t) {
        if (t < NT - 1) CP_WAIT1(); else CP_WAIT0();
        __syncwarp();
        float (*bufc)[PITCH] = buf[t & 1];
        if (GUARD && t < WTILES)
            compute_tile_guard(t, lane, skipA, bufc, mu2, s22, c);
        else if (t < WTILES)
            compute_tile2<false>(lane, bufc, sg, mu2, s22, c);
        else
            compute_tile2<true>(lane, bufc, sg, mu2, s22, c);
        __syncwarp();
        if (t + 2 < NT)       stage_tile<GUARD>(t + 2, wcb, lane, y, buf[t & 1]);
        else if (t >= WTILES) flush_tile(t, wcb, lane, bufc, sg, out);
    }
}

__global__ __launch_bounds__(TPB)
void argas_kernel(
    const float* __restrict__ y,
    const float* __restrict__ p_lastmu,  const float* __restrict__ p_lastsig,
    const float* __restrict__ p_amu,     const float* __restrict__ p_as,
    const float* __restrict__ p_bmu,     const float* __restrict__ p_bs,
    const float* __restrict__ p_wmu,     const float* __restrict__ p_ws,
    const float* __restrict__ p_nu,      const float* __restrict__ p_str,
    float* __restrict__ out)
{
    __shared__ float buf[WPB][2][CPW][PITCH];   // per-warp double-buffered tiles
    __shared__ float sg[WPB][CPW][PITCH];       // per-warp s2 staging (emit)

    const int warp = threadIdx.x >> 5;
    const int lane = threadIdx.x & 31;
    const int wcb  = (blockIdx.x * WPB + warp) * CPW;   // warp's chain base

    C c;
    const float nu       = *p_nu;
    const float strength = *p_str;
    const float amu  = (*p_amu) * strength;
    const float as_  = (*p_as)  * strength;
    const float bmu  = *p_bmu;
    const float bs   = *p_bs;
    const float nup1 = nu + 1.0f;
    c.nu  = nu;
    c.Amu = bmu * amu * nup1;
    c.As  = bs  * as_ * nup1;
    c.bmu = bmu;
    c.Bs  = bs * (1.0f - as_);
    c.wmu = *p_wmu;
    c.ws  = *p_ws;
    c.neg1 = pack2(-1.0f, -1.0f);
    c.nu2  = pack2(c.nu,  c.nu);
    c.amu2 = pack2(c.Amu, c.Amu);
    c.as2  = pack2(c.As,  c.As);
    c.bmu2 = pack2(c.bmu, c.bmu);
    c.bs2  = pack2(c.Bs,  c.Bs);
    c.wmu2 = pack2(c.wmu, c.wmu);
    c.ws2  = pack2(c.ws,  c.ws);

    const float mu0 = *p_lastmu;   // chains whose warmup reaches before idx 0
    const float s20 = *p_lastsig;  // skip those steps; they start exact.
    const u64 mu2 = pack2(mu0, mu0);
    const u64 s22 = pack2(s20, s20);

    // chain A = wcb+lane, chain B = wcb+32+lane. Only chains 0..3 (warp 0,
    // lanes 0..3, A side) have warmup windows reaching before index 0.
    const int skipA = WARM - (wcb + lane) * CHUNK;   // >0 only for those

    if (wcb == 0)
        run_warp<true >(wcb, lane, y, out, buf[warp], sg[warp], mu2, s22, c, skipA);
    else
        run_warp<false>(wcb, lane, y, out, buf[warp], sg[warp], mu2, s22, c, skipA);
}

extern "C" void kernel_launch(void* const* d_in, const int* in_sizes, int n_in,
                              void* d_out, int out_size) {
    const float* y = (const float*)d_in[0];
    argas_kernel<<<NBLK, TPB>>>(
        y,
        (const float*)d_in[1],  (const float*)d_in[2],
        (const float*)d_in[3],  (const float*)d_in[4],
        (const float*)d_in[5],  (const float*)d_in[6],
        (const float*)d_in[7],  (const float*)d_in[8],
        (const float*)d_in[9],  (const float*)d_in[10],
        (float*)d_out);
}

// round 8
// speedup vs baseline: 1.5626x; 1.5626x over previous
#include <cuda_runtime.h>
#include <cstdint>

#define KTOT   4194304
#define CHUNK  64                       // outputs per chain
#define WARM   128                      // warmup (redundant) steps per chain
#define TS     32                       // steps per tile
#define NT     ((WARM + CHUNK) / TS)    // 6 tiles
#define WTILES (WARM / TS)              // 4 warmup tiles
#define NCH    (KTOT / CHUNK)           // 65536 chains (1 per thread)
#define WPB    2                        // warps per block
#define TPB    (WPB * 32)
#define NWARP  (NCH / 32)               // 2048 warps
#define NBLK   (NWARP / WPB)            // 1024 blocks
#define PITCH  34                       // smem row pitch in floats (8B-aligned)

__device__ __forceinline__ float frcp_ap(float x) {
    float r; asm("rcp.approx.ftz.f32 %0, %1;" : "=f"(r) : "f"(x)); return r;
}
__device__ __forceinline__ float fsqrt_ap(float x) {
    float r; asm("sqrt.approx.f32 %0, %1;" : "=f"(r) : "f"(x)); return r;
}
__device__ __forceinline__ void cp_async8(uint32_t dst, const float* src) {
    asm volatile("cp.async.ca.shared.global [%0], [%1], 8;" :: "r"(dst), "l"(src));
}
#define CP_COMMIT() asm volatile("cp.async.commit_group;" ::: "memory")
#define CP_WAIT1()  asm volatile("cp.async.wait_group 1;"  ::: "memory")
#define CP_WAIT0()  asm volatile("cp.async.wait_group 0;"  ::: "memory")

struct P { float nu, Amu, As, bmu, Bs, wmu, ws; };

__device__ __forceinline__ void gas_step(const float y, float& mu, float& s2, const P& p) {
    // scale*r = (nu+1)*s2*r / (nu*s2 + r^2): one rcp, 10 fma-pipe ops
    const float r_  = y - mu;
    const float rr  = r_ * r_;
    const float d   = fmaf(p.nu, s2, rr);
    const float q   = frcp_ap(d);
    const float s2r = s2 * r_;
    const float mb  = fmaf(p.bmu, mu, p.wmu);   // off critical path
    const float sb  = fmaf(p.Bs,  s2, p.ws);    // off critical path
    const float N   = s2r * q;
    mu = fmaf(p.Amu, N, mb);
    s2 = fmaf(p.As, N * r_, sb);
}

// Prologue-only burst staging of a tile (32 chains x 32 steps) via 8B cp.async.
// lane -> row r0 = lane>>4 (0/1), col = (lane&15)*2; k advances 2 rows.
template<bool GUARD>
__device__ __forceinline__ void stage_tile_burst(
    const int tau, const int wcb, const int lane,
    const float* __restrict__ y, float (*buf)[PITCH])
{
    const int r0  = lane >> 4;
    const int col = (lane & 15) * 2;
    uint32_t dst = (uint32_t)__cvta_generic_to_shared(&buf[r0][col]);
    const int gbase = (wcb + r0) * CHUNK - WARM + tau * TS + col;
    #pragma unroll
    for (int k = 0; k < 16; ++k) {
        int g = gbase + k * (2 * CHUNK);
        if (GUARD) g = max(g, 0);      // pre-t0 slots: skipped anyway
        cp_async8(dst + k * (2 * PITCH * 4), y + g);
    }
    CP_COMMIT();
}

// One tile of compute (TS steps), with (a) LDS pipelined one iteration ahead
// and (b) the NEXT-next tile's cp.asyncs spread through the loop (1 per 2
// steps) so the LSU never sees a burst that queues ahead of critical LDS.
template<bool GUARD, bool EMIT, bool STAGE>
__device__ __forceinline__ void compute_tile(
    const int tau, const int lane, const int skip,
    float (*bufc)[PITCH], float (*sg)[PITCH],
    const float* __restrict__ y, const int gb_next, const uint32_t sd_next,
    float& mu, float& s2, const P& p)
{
    float2 cur = *reinterpret_cast<const float2*>(&bufc[lane][0]);
    #pragma unroll
    for (int j = 0; j < TS / 2; ++j) {
        float2 nxt = cur;
        if (j < TS / 2 - 1)
            nxt = *reinterpret_cast<const float2*>(&bufc[lane][2 * j + 2]);
        if (STAGE) {                       // 1 cp.async per 2 steps (16 total)
            int g = gb_next + j * (2 * CHUNK);
            if (GUARD) g = max(g, 0);
            cp_async8(sd_next + j * (2 * PITCH * 4), y + g);
        }
        if (GUARD) {
            if (tau * TS + 2 * j     >= skip) gas_step(cur.x, mu, s2, p);
            if (tau * TS + 2 * j + 1 >= skip) gas_step(cur.y, mu, s2, p);
        } else {
            gas_step(cur.x, mu, s2, p);
            const float m0 = mu, v0 = s2;
            gas_step(cur.y, mu, s2, p);
            if (EMIT) {   // mu in place of dead input; raw s2 (sqrt at flush)
                *reinterpret_cast<float2*>(&bufc[lane][2 * j]) = make_float2(m0, mu);
                *reinterpret_cast<float2*>(&sg[lane][2 * j])   = make_float2(v0, s2);
            }
        }
        cur = nxt;
    }
    if (STAGE) CP_COMMIT();
}

// Coalesced flush of an emit tile: mu from bufc (in-place), sigma=sqrt(s2).
__device__ __forceinline__ void flush_tile(
    const int tau, const int wcb, const int lane,
    const float (*bufc)[PITCH], const float (*sg)[PITCH], float* __restrict__ out)
{
    const int col = (lane & 15) * 2;
    const int r0  = lane >> 4;
    const int ob  = (tau - WTILES) * TS;
    #pragma unroll
    for (int k = 0; k < 16; ++k) {
        const int row = 2 * k + r0;
        const float2 m = *reinterpret_cast<const float2*>(&bufc[row][col]);
        float2 g = *reinterpret_cast<const float2*>(&sg[row][col]);
        g.x = fsqrt_ap(g.x); g.y = fsqrt_ap(g.y);
        const int gi = (wcb + row) * CHUNK + ob + col;
        *reinterpret_cast<float2*>(&out[gi])        = m;
        *reinterpret_cast<float2*>(&out[KTOT + gi]) = g;
    }
}

template<bool GUARD>
__device__ __forceinline__ void run_warp(
    const int wcb, const int lane,
    const float* __restrict__ y, float* __restrict__ out,
    float (*buf)[TS][PITCH],               // [3][32][PITCH] triple buffer
    float mu, float s2, const P& p, const int skip)
{
    const int r0  = lane >> 4;
    const int col = (lane & 15) * 2;

    stage_tile_burst<GUARD>(0, wcb, lane, y, buf[0]);
    stage_tile_burst<GUARD>(1, wcb, lane, y, buf[1]);

    #pragma unroll 1
    for (int t = 0; t < NT; ++t) {
        if (t < NT - 1) CP_WAIT1(); else CP_WAIT0();
        __syncwarp();
        float (*bufc)[PITCH] = buf[t % 3];
        float (*bufn)[PITCH] = buf[(t + 2) % 3];   // staging target / free buf
        const int gb_next = (wcb + r0) * CHUNK - WARM + (t + 2) * TS + col;
        const uint32_t sd_next =
            (uint32_t)__cvta_generic_to_shared(&bufn[r0][col]);

        if (t < WTILES) {                           // tiles 0..3: stage t+2
            if (GUARD)
                compute_tile<true,  false, true>(t, lane, skip, bufc, bufn,
                                                 y, gb_next, sd_next, mu, s2, p);
            else
                compute_tile<false, false, true>(t, lane, skip, bufc, bufn,
                                                 y, gb_next, sd_next, mu, s2, p);
        } else {                                    // tiles 4,5: emit, no stage
            float (*sgp)[PITCH] = bufn;             // (t+2)%3 buffer is free
            compute_tile<false, true, false>(t, lane, skip, bufc, sgp,
                                             y, gb_next, sd_next, mu, s2, p);
            __syncwarp();
            flush_tile(t, wcb, lane, bufc, sgp, out);
            __syncwarp();   // flush reads done before next tile reuses sg buf
        }
    }
}

__global__ __launch_bounds__(TPB)
void argas_kernel(
    const float* __restrict__ y,
    const float* __restrict__ p_lastmu,  const float* __restrict__ p_lastsig,
    const float* __restrict__ p_amu,     const float* __restrict__ p_as,
    const float* __restrict__ p_bmu,     const float* __restrict__ p_bs,
    const float* __restrict__ p_wmu,     const float* __restrict__ p_ws,
    const float* __restrict__ p_nu,      const float* __restrict__ p_str,
    float* __restrict__ out)
{
    __shared__ float buf[WPB][3][TS][PITCH];   // per-warp triple-buffered tiles

    const int warp  = threadIdx.x >> 5;
    const int lane  = threadIdx.x & 31;
    const int wcb   = (blockIdx.x * WPB + warp) * 32;   // warp's chain base
    const int chain = wcb + lane;

    P p;
    const float nu       = *p_nu;
    const float strength = *p_str;
    const float amu  = (*p_amu) * strength;
    const float as_  = (*p_as)  * strength;
    const float bmu  = *p_bmu;
    const float bs   = *p_bs;
    const float nup1 = nu + 1.0f;
    p.nu  = nu;
    p.Amu = bmu * amu * nup1;
    p.As  = bs  * as_ * nup1;
    p.bmu = bmu;
    p.Bs  = bs * (1.0f - as_);
    p.wmu = *p_wmu;
    p.ws  = *p_ws;

    const float mu0 = *p_lastmu;   // chains whose warmup reaches before idx 0
    const float s20 = *p_lastsig;  // skip those steps; they start exact.

    const int skip = WARM - chain * CHUNK;   // >0 only for chains 0,1 (warp 0)

    if (wcb == 0)
        run_warp<true >(wcb, lane, y, out, buf[warp], mu0, s20, p, skip);
    else
        run_warp<false>(wcb, lane, y, out, buf[warp], mu0, s20, p, skip);
}

extern "C" void kernel_launch(void* const* d_in, const int* in_sizes, int n_in,
                              void* d_out, int out_size) {
    const float* y = (const float*)d_in[0];
    argas_kernel<<<NBLK, TPB>>>(
        y,
        (const float*)d_in[1],  (const float*)d_in[2],
        (const float*)d_in[3],  (const float*)d_in[4],
        (const float*)d_in[5],  (const float*)d_in[6],
        (const float*)d_in[7],  (const float*)d_in[8],
        (const float*)d_in[9],  (const float*)d_in[10],
        (float*)d_out);
}